// round 1
// baseline (speedup 1.0000x reference)
#include <cuda_runtime.h>
#include <cuda_bf16.h>

#define BATCH 256
#define CCH   256       // C
#define LSQ   512       // L
#define TWOC  512       // 2C

// Scratch: G = Wp @ x  per batch, [B, 2C, L]  (268 MB, zero-init bss)
__device__ float g_G[(size_t)BATCH * TWOC * LSQ];
// Repacked weights: Wp[m,k]; m<C: W1[m,k]=W[m,k]; m>=C: W2[m-C,k]=W[m-C, C+k]
__device__ float g_Wp[TWOC * CCH];

// ---------------------------------------------------------------------------
// Kernel 1: repack W [C, 2C] -> Wp [2C, C]
// ---------------------------------------------------------------------------
__global__ void prep_kernel(const float* __restrict__ W) {
    int i = blockIdx.x * blockDim.x + threadIdx.x;
    if (i < TWOC * CCH) {
        int m = i / CCH;
        int k = i - m * CCH;
        float v = (m < CCH) ? W[m * TWOC + k]
                            : W[(m - CCH) * TWOC + CCH + k];
        g_Wp[i] = v;
    }
}

// ---------------------------------------------------------------------------
// Kernel 2: batched GEMM  G[b] = Wp @ x[b]
//   A = Wp [512 x 256]   (shared across batches)
//   B = x[b] [256 x 512] row-major
//   C = G[b] [512 x 512]
// Tiles: BM=128, BN=64, BK=16; 256 threads; TM=8, TN=4 per thread.
// ---------------------------------------------------------------------------
#define BM 128
#define BN 64
#define BK 16
#define TM 8
#define TN 4

__global__ __launch_bounds__(256, 4)
void gemm_kernel(const float* __restrict__ x) {
    __shared__ float As[BK][BM + 4];   // As[k][m]
    __shared__ float Bs[BK][BN + 4];   // Bs[k][n]

    const int b  = blockIdx.z;
    const int m0 = blockIdx.y * BM;
    const int n0 = blockIdx.x * BN;
    const int tid = threadIdx.x;

    const float* __restrict__ Bx = x + (size_t)b * CCH * LSQ;
    float*       __restrict__ Gb = g_G + (size_t)b * TWOC * LSQ;

    // thread tile coords: tx over N (16 cols of TN=4), ty over M (16 rows of TM=8)
    const int tx = tid & 15;
    const int ty = tid >> 4;

    // global load coords
    const int a_k = tid & 15;          // 0..15
    const int a_m = tid >> 4;          // 0..15  (stride 16 over 128 rows -> 8 loads)
    const int b_n = tid & 63;          // 0..63
    const int b_k = tid >> 6;          // 0..3   (stride 4 over 16 rows -> 4 loads)

    float acc[TM][TN];
#pragma unroll
    for (int i = 0; i < TM; i++)
#pragma unroll
        for (int j = 0; j < TN; j++) acc[i][j] = 0.f;

    for (int kt = 0; kt < CCH; kt += BK) {
        // load A tile: 128x16 -> As[k][m]
#pragma unroll
        for (int i = 0; i < 8; i++) {
            int m = a_m + i * 16;
            As[a_k][m] = g_Wp[(m0 + m) * CCH + kt + a_k];
        }
        // load B tile: 16x64 -> Bs[k][n]
#pragma unroll
        for (int i = 0; i < 4; i++) {
            int k = b_k + i * 4;
            Bs[k][b_n] = Bx[(size_t)(kt + k) * LSQ + n0 + b_n];
        }
        __syncthreads();

#pragma unroll
        for (int kk = 0; kk < BK; kk++) {
            float4 a0 = *(const float4*)&As[kk][ty * TM];
            float4 a1 = *(const float4*)&As[kk][ty * TM + 4];
            float4 bb = *(const float4*)&Bs[kk][tx * TN];
            float a[TM] = {a0.x, a0.y, a0.z, a0.w, a1.x, a1.y, a1.z, a1.w};
            float bv[TN] = {bb.x, bb.y, bb.z, bb.w};
#pragma unroll
            for (int i = 0; i < TM; i++)
#pragma unroll
                for (int j = 0; j < TN; j++)
                    acc[i][j] = fmaf(a[i], bv[j], acc[i][j]);
        }
        __syncthreads();
    }

    // epilogue: write G
#pragma unroll
    for (int i = 0; i < TM; i++) {
        int m = m0 + ty * TM + i;
        float4 v = make_float4(acc[i][0], acc[i][1], acc[i][2], acc[i][3]);
        *(float4*)&Gb[(size_t)m * LSQ + n0 + tx * TN] = v;
    }
}

// ---------------------------------------------------------------------------
// Kernel 3: per-(b,c) fused combine + InstanceNorm + ReLU
//   y[l] = G1[b,c,l] + (idx[b,l] < L ? G2[b,c,idx] : 0) + bias[c]
//   out  = relu((y - mean) * rsqrt(var + eps))
// One block (256 threads) per (b,c) row; 2 elements per thread.
// ---------------------------------------------------------------------------
__global__ __launch_bounds__(256)
void norm_kernel(const int* __restrict__ idx,
                 const float* __restrict__ bias,
                 float* __restrict__ out) {
    const int c = blockIdx.x;
    const int b = blockIdx.y;
    const int tid = threadIdx.x;

    const float* __restrict__ G1 = g_G + ((size_t)b * TWOC + c) * LSQ;
    const float* __restrict__ G2 = g_G + ((size_t)b * TWOC + CCH + c) * LSQ;
    const int*   __restrict__ id = idx + (size_t)b * LSQ;
    const float bv = __ldg(&bias[c]);

    float v[2];
    float s = 0.f, s2 = 0.f;
#pragma unroll
    for (int i = 0; i < 2; i++) {
        int l = tid + i * 256;
        int j = id[l];
        float g2 = (j < LSQ) ? G2[j] : 0.f;
        float y = G1[l] + g2 + bv;
        v[i] = y;
        s  += y;
        s2 += y * y;
    }

    // block reduce (256 threads = 8 warps)
    __shared__ float rs[8], rs2[8];
#pragma unroll
    for (int o = 16; o > 0; o >>= 1) {
        s  += __shfl_xor_sync(0xffffffffu, s,  o);
        s2 += __shfl_xor_sync(0xffffffffu, s2, o);
    }
    int wid = tid >> 5, lane = tid & 31;
    if (lane == 0) { rs[wid] = s; rs2[wid] = s2; }
    __syncthreads();
    if (wid == 0) {
        float a  = (lane < 8) ? rs[lane]  : 0.f;
        float a2 = (lane < 8) ? rs2[lane] : 0.f;
#pragma unroll
        for (int o = 4; o > 0; o >>= 1) {
            a  += __shfl_xor_sync(0xffffffffu, a,  o);
            a2 += __shfl_xor_sync(0xffffffffu, a2, o);
        }
        if (lane == 0) { rs[0] = a; rs2[0] = a2; }
    }
    __syncthreads();

    const float inv_l = 1.0f / (float)LSQ;
    float mu  = rs[0] * inv_l;
    float var = rs2[0] * inv_l - mu * mu;
    float rstd = rsqrtf(var + 1e-5f);

    float* __restrict__ o = out + ((size_t)b * CCH + c) * LSQ;
#pragma unroll
    for (int i = 0; i < 2; i++) {
        int l = tid + i * 256;
        float r = (v[i] - mu) * rstd;
        o[l] = fmaxf(r, 0.f);
    }
}

// ---------------------------------------------------------------------------
// launch
// ---------------------------------------------------------------------------
extern "C" void kernel_launch(void* const* d_in, const int* in_sizes, int n_in,
                              void* d_out, int out_size) {
    const float* x    = (const float*)d_in[0];   // [B, C, L]
    const int*   idx  = (const int*)d_in[1];     // [B, L]
    const float* W    = (const float*)d_in[2];   // [C, 2C]
    const float* bias = (const float*)d_in[3];   // [C]
    float* out = (float*)d_out;                  // [B, C, L]

    // 1) repack W
    prep_kernel<<<(TWOC * CCH + 255) / 256, 256>>>(W);

    // 2) batched GEMM: grid (N/BN=8, M/BM=4, B=256)
    dim3 ggrid(LSQ / BN, TWOC / BM, BATCH);
    gemm_kernel<<<ggrid, 256>>>(x);

    // 3) fused combine + instance-norm + relu: grid (C, B)
    dim3 ngrid(CCH, BATCH);
    norm_kernel<<<ngrid, 256>>>(idx, bias, out);
}

// round 3
// speedup vs baseline: 1.6774x; 1.6774x over previous
#include <cuda_runtime.h>
#include <cuda_bf16.h>
#include <cstdint>

#define BATCH 256
#define CCH   256       // C
#define LSQ   512       // L
#define TWOC  512       // 2C
#define KEFF  768       // 3 * C  (wh@xh | wl@xh | wh@xl)

// ---------------------------------------------------------------------------
// Device scratch (allocation-free rule: __device__ globals)
// ---------------------------------------------------------------------------
__device__ float          g_G[(size_t)BATCH * TWOC * LSQ];        // 268 MB
__device__ __nv_bfloat16  g_A[TWOC * KEFF];                        // 768 KB
__device__ __nv_bfloat16  g_xh[(size_t)BATCH * LSQ * CCH];         // 67 MB  [b, l, c]
__device__ __nv_bfloat16  g_xl[(size_t)BATCH * LSQ * CCH];         // 67 MB  [b, l, c]

// ---------------------------------------------------------------------------
// helpers
// ---------------------------------------------------------------------------
__device__ __forceinline__ uint32_t s2u(const void* p) {
    uint32_t a;
    asm("{ .reg .u64 t; cvta.to.shared.u64 t, %1; cvt.u32.u64 %0, t; }" : "=r"(a) : "l"(p));
    return a;
}
__device__ __forceinline__ void cpasync16(uint32_t dst, const void* src) {
    asm volatile("cp.async.cg.shared.global [%0], [%1], 16;" :: "r"(dst), "l"(src) : "memory");
}
__device__ __forceinline__ void cp_commit() {
    asm volatile("cp.async.commit_group;" ::: "memory");
}
__device__ __forceinline__ void cp_wait1() {
    asm volatile("cp.async.wait_group 1;" ::: "memory");
}
__device__ __forceinline__ void ldm_x4(uint32_t* r, uint32_t addr) {
    asm volatile("ldmatrix.sync.aligned.m8n8.x4.shared.b16 {%0,%1,%2,%3}, [%4];"
                 : "=r"(r[0]), "=r"(r[1]), "=r"(r[2]), "=r"(r[3]) : "r"(addr));
}
__device__ __forceinline__ void mma_bf16(float* c, const uint32_t* a, uint32_t b0, uint32_t b1) {
    asm volatile(
        "mma.sync.aligned.m16n8k16.row.col.f32.bf16.bf16.f32 "
        "{%0,%1,%2,%3}, {%4,%5,%6,%7}, {%8,%9}, {%0,%1,%2,%3};"
        : "+f"(c[0]), "+f"(c[1]), "+f"(c[2]), "+f"(c[3])
        : "r"(a[0]), "r"(a[1]), "r"(a[2]), "r"(a[3]), "r"(b0), "r"(b1));
}

// ---------------------------------------------------------------------------
// Kernel 1: build A = [wh | wl | wh]  (512 x 768 bf16), from W [C, 2C]
// ---------------------------------------------------------------------------
__global__ void prep_kernel(const float* __restrict__ W) {
    int i = blockIdx.x * blockDim.x + threadIdx.x;
    if (i >= TWOC * KEFF) return;
    int m = i / KEFF;
    int keff = i - m * KEFF;
    int k = keff & 255;
    float w = (m < CCH) ? W[m * TWOC + k] : W[(m - CCH) * TWOC + CCH + k];
    __nv_bfloat16 wh = __float2bfloat16(w);
    __nv_bfloat16 out;
    if (keff < 512 && keff >= 256)
        out = __float2bfloat16(w - __bfloat162float(wh));   // wl
    else
        out = wh;
    g_A[i] = out;
}

// ---------------------------------------------------------------------------
// Kernel 2: transpose + split  x[b,c,l] f32  ->  xh[b,l,c], xl[b,l,c] bf16
// ---------------------------------------------------------------------------
__global__ __launch_bounds__(256)
void conv_kernel(const float* __restrict__ x) {
    __shared__ float tile[32][33];
    int b  = blockIdx.z;
    int l0 = blockIdx.x * 32;
    int c0 = blockIdx.y * 32;
    int tx = threadIdx.x & 31, ty = threadIdx.x >> 5;   // ty 0..7

    const float* xb = x + ((size_t)b * CCH + c0) * LSQ + l0;
#pragma unroll
    for (int i = 0; i < 4; i++) {
        int c = ty + i * 8;
        tile[c][tx] = xb[(size_t)c * LSQ + tx];
    }
    __syncthreads();
    size_t obase = ((size_t)b * LSQ + l0) * CCH + c0;
#pragma unroll
    for (int i = 0; i < 4; i++) {
        int l = ty + i * 8;
        float v = tile[tx][l];
        __nv_bfloat16 h = __float2bfloat16(v);
        g_xh[obase + (size_t)l * CCH + tx] = h;
        g_xl[obase + (size_t)l * CCH + tx] = __float2bfloat16(v - __bfloat162float(h));
    }
}

// ---------------------------------------------------------------------------
// Kernel 3: mma.sync bf16 GEMM  G[b] (512x512 f32) = A (512x768) @ B[b]^T
//   CTA tile 128x128, BK=32, 3-stage cp.async, 256 threads, warp grid 2x4.
//   smem rows: 32 bf16 = 64B data, stride 80B  (80*r mod 128 hits all eight
//   16B offsets -> ldmatrix conflict-free, no swizzle needed)
// ---------------------------------------------------------------------------
#define BK      32
#define STRIDE  80
#define A_TILE  (128 * STRIDE)           // 10240
#define STAGE_B (2 * A_TILE)             // 20480 (A then B)
#define STAGES  3
#define GSMEM   (STAGES * STAGE_B)       // 61440
#define NKT     (KEFF / BK)              // 24

__global__ __launch_bounds__(256)
void gemm_kernel() {
    extern __shared__ char smem[];
    const uint32_t sb = s2u(smem);
    const int tid = threadIdx.x;
    const int wid = tid >> 5;
    const int l   = tid & 31;
    const int b   = blockIdx.z;
    const int m0  = blockIdx.y * 128;
    const int n0  = blockIdx.x * 128;

    const int warp_m = wid & 1;          // 0..1  (64 rows each)
    const int warp_n = wid >> 1;         // 0..3  (32 cols each)

    // ldmatrix lane offsets (within a stage)
    const uint32_t a_lm = (uint32_t)(warp_m * 64 + (l & 15)) * STRIDE + ((l >> 4) * 16);
    const uint32_t b_lm = (uint32_t)(warp_n * 32 + (l & 7) + ((l >> 4) << 3)) * STRIDE
                        + (((l >> 3) & 1) * 16);

    // global load coords: 512 16B-chunks per tile, 2 per thread
    const int g_row = tid >> 2;          // 0..63  (+64 for second)
    const int g_col = tid & 3;           // 16B column

    float acc[4][4][4];
#pragma unroll
    for (int i = 0; i < 4; i++)
#pragma unroll
        for (int j = 0; j < 4; j++)
#pragma unroll
            for (int k = 0; k < 4; k++) acc[i][j][k] = 0.f;

    auto load_tile = [&](int kt, int s) {
        const uint32_t base = sb + s * STAGE_B;
        // A: rows m0+row, cols kt*32 + g_col*8
#pragma unroll
        for (int i = 0; i < 2; i++) {
            int row = g_row + i * 64;
            const void* src = g_A + (size_t)(m0 + row) * KEFF + kt * BK + g_col * 8;
            cpasync16(base + row * STRIDE + g_col * 16, src);
        }
        // B: rows n0+row from xh/xl
        const __nv_bfloat16* xs = (kt < 16) ? g_xh : g_xl;
        const int kb = (kt & 7) * BK;
#pragma unroll
        for (int i = 0; i < 2; i++) {
            int row = g_row + i * 64;
            const void* src = xs + ((size_t)b * LSQ + n0 + row) * CCH + kb + g_col * 8;
            cpasync16(base + A_TILE + row * STRIDE + g_col * 16, src);
        }
        cp_commit();
    };

    load_tile(0, 0);
    load_tile(1, 1);

    for (int kt = 0; kt < NKT; kt++) {
        const int s = kt % STAGES;
        cp_wait1();
        __syncthreads();
        if (kt + 2 < NKT) load_tile(kt + 2, (kt + 2) % STAGES);
        else cp_commit();                      // keep group counts consistent

        const uint32_t abase = sb + s * STAGE_B + a_lm;
        const uint32_t bbase = sb + s * STAGE_B + A_TILE + b_lm;
#pragma unroll
        for (int k16 = 0; k16 < 2; k16++) {
            uint32_t af[4][4], bf[2][4];
#pragma unroll
            for (int mi = 0; mi < 4; mi++)
                ldm_x4(af[mi], abase + mi * 16 * STRIDE + k16 * 32);
#pragma unroll
            for (int bi = 0; bi < 2; bi++)
                ldm_x4(bf[bi], bbase + bi * 16 * STRIDE + k16 * 32);
#pragma unroll
            for (int mi = 0; mi < 4; mi++)
#pragma unroll
                for (int ni = 0; ni < 4; ni++)
                    mma_bf16(acc[mi][ni], af[mi],
                             bf[ni >> 1][(ni & 1) * 2], bf[ni >> 1][(ni & 1) * 2 + 1]);
        }
        __syncthreads();
    }

    // epilogue: direct stores
    const int grp  = l >> 2;             // row within 8
    const int quad = l & 3;              // col pair
#pragma unroll
    for (int mi = 0; mi < 4; mi++) {
        int r0 = m0 + warp_m * 64 + mi * 16 + grp;
#pragma unroll
        for (int ni = 0; ni < 4; ni++) {
            int col = n0 + warp_n * 32 + ni * 8 + quad * 2;
            float* p0 = g_G + ((size_t)b * TWOC + r0) * LSQ + col;
            float* p1 = p0 + 8 * LSQ;
            *(float2*)p0 = make_float2(acc[mi][ni][0], acc[mi][ni][1]);
            *(float2*)p1 = make_float2(acc[mi][ni][2], acc[mi][ni][3]);
        }
    }
}

// ---------------------------------------------------------------------------
// Kernel 4: fused combine + InstanceNorm + ReLU
// ---------------------------------------------------------------------------
__global__ __launch_bounds__(256)
void norm_kernel(const int* __restrict__ idx,
                 const float* __restrict__ bias,
                 float* __restrict__ out) {
    const int c = blockIdx.x;
    const int b = blockIdx.y;
    const int tid = threadIdx.x;

    const float* __restrict__ G1 = g_G + ((size_t)b * TWOC + c) * LSQ;
    const float* __restrict__ G2 = g_G + ((size_t)b * TWOC + CCH + c) * LSQ;
    const int*   __restrict__ id = idx + (size_t)b * LSQ;
    const float bv = __ldg(&bias[c]);

    float v[2];
    float s = 0.f, s2 = 0.f;
#pragma unroll
    for (int i = 0; i < 2; i++) {
        int l = tid + i * 256;
        int j = id[l];
        float g2 = (j < LSQ) ? G2[j] : 0.f;
        float y = G1[l] + g2 + bv;
        v[i] = y;
        s  += y;
        s2 += y * y;
    }

    __shared__ float rs[8], rs2[8];
#pragma unroll
    for (int o = 16; o > 0; o >>= 1) {
        s  += __shfl_xor_sync(0xffffffffu, s,  o);
        s2 += __shfl_xor_sync(0xffffffffu, s2, o);
    }
    int wid = tid >> 5, lane = tid & 31;
    if (lane == 0) { rs[wid] = s; rs2[wid] = s2; }
    __syncthreads();
    if (wid == 0) {
        float a  = (lane < 8) ? rs[lane]  : 0.f;
        float a2 = (lane < 8) ? rs2[lane] : 0.f;
#pragma unroll
        for (int o = 4; o > 0; o >>= 1) {
            a  += __shfl_xor_sync(0xffffffffu, a,  o);
            a2 += __shfl_xor_sync(0xffffffffu, a2, o);
        }
        if (lane == 0) { rs[0] = a; rs2[0] = a2; }
    }
    __syncthreads();

    const float inv_l = 1.0f / (float)LSQ;
    float mu  = rs[0] * inv_l;
    float var = rs2[0] * inv_l - mu * mu;
    float rstd = rsqrtf(var + 1e-5f);

    float* __restrict__ o = out + ((size_t)b * CCH + c) * LSQ;
#pragma unroll
    for (int i = 0; i < 2; i++) {
        int l = tid + i * 256;
        float r = (v[i] - mu) * rstd;
        o[l] = fmaxf(r, 0.f);
    }
}

// ---------------------------------------------------------------------------
// launch
// ---------------------------------------------------------------------------
extern "C" void kernel_launch(void* const* d_in, const int* in_sizes, int n_in,
                              void* d_out, int out_size) {
    const float* x    = (const float*)d_in[0];   // [B, C, L]
    const int*   idx  = (const int*)d_in[1];     // [B, L]
    const float* W    = (const float*)d_in[2];   // [C, 2C]
    const float* bias = (const float*)d_in[3];   // [C]
    float* out = (float*)d_out;                  // [B, C, L]

    cudaFuncSetAttribute(gemm_kernel, cudaFuncAttributeMaxDynamicSharedMemorySize, GSMEM);

    // 1) A = [wh | wl | wh]
    prep_kernel<<<(TWOC * KEFF + 255) / 256, 256>>>(W);

    // 2) transpose + bf16 split: grid (L/32, C/32, B)
    dim3 cgrid(LSQ / 32, CCH / 32, BATCH);
    conv_kernel<<<cgrid, 256>>>(x);

    // 3) mma.sync GEMM: grid (4 n-tiles, 4 m-tiles, B)
    dim3 ggrid(LSQ / 128, TWOC / 128, BATCH);
    gemm_kernel<<<ggrid, 256, GSMEM>>>();

    // 4) fused combine + instance-norm + relu
    dim3 ngrid(CCH, BATCH);
    norm_kernel<<<ngrid, 256>>>(idx, bias, out);
}